// round 13
// baseline (speedup 1.0000x reference)
#include <cuda_runtime.h>
#include <math.h>
#include <stdint.h>

// Shapes
#define V_SZ 50257
#define E_SZ 512
#define H_SZ 1024
#define C_SZ 1024
#define S_SZ 2048
#define NRC 8                // row-chunks for wsum partials
#define NBLK 148             // persistent blocks (1 per SM, single wave)
#define TPB 1024
#define ROWS_PER_BLK 340     // ceil(V_SZ / NBLK)
#define CHUNK_ROWS 16
#define CHUNK_BYTES (CHUNK_ROWS * 4096)      // 64 KB
#define NSTAGE 3
#define DYN_SMEM (NSTAGE * CHUNK_BYTES)      // 192 KB ring

// ---------------- scratch (device globals) --------------------------------------
__device__ __align__(16) float g_x[H_SZ];               // h of layer 0
__device__ __align__(16) float g_q[H_SZ];               // rnn_output
__device__ __align__(16) float g_u[3][C_SZ];            // W^T q per head
__device__            float g_bq[3];                    // b . q per head
__device__ __align__(16) float g_e[3][S_SZ];            // attention logits
__device__ __align__(16) float g_wpart[3][NRC][C_SZ];   // wsum row-chunk partials
__device__ __align__(16) float g_co[H_SZ];              // concat_out

// ---------------- device-wide barrier (sense-reversal, replay-safe) --------------
__device__ unsigned g_barc;
__device__ volatile unsigned g_barg;

__device__ __forceinline__ void gbar() {
    __syncthreads();
    if (threadIdx.x == 0) {
        __threadfence();
        unsigned gen = g_barg;
        if (atomicAdd(&g_barc, 1u) == NBLK - 1) {
            atomicExch(&g_barc, 0u);
            __threadfence();
            g_barg = gen + 1;
        } else {
            while (g_barg == gen) { __nanosleep(64); }
        }
        __threadfence();
    }
    __syncthreads();
}

// ---------------- helpers --------------------------------------------------------
__device__ __forceinline__ float warp_sum(float v) {
#pragma unroll
    for (int o = 16; o; o >>= 1) v += __shfl_xor_sync(0xffffffffu, v, o);
    return v;
}
__device__ __forceinline__ float warp_max(float v) {
#pragma unroll
    for (int o = 16; o; o >>= 1) v = fmaxf(v, __shfl_xor_sync(0xffffffffu, v, o));
    return v;
}
__device__ __forceinline__ float sigf(float x) { return 1.0f / (1.0f + expf(-x)); }
__device__ __forceinline__ float dot4(float4 w, float4 v) {
    return w.x * v.x + w.y * v.y + w.z * v.z + w.w * v.w;
}
__device__ __forceinline__ uint32_t smaddr(const void* p) {
    return (uint32_t)__cvta_generic_to_shared(p);
}
__device__ __forceinline__ void mbar_wait(uint32_t mbar, uint32_t parity) {
    uint32_t done;
    do {
        asm volatile(
            "{\n\t.reg .pred p;\n\t"
            "mbarrier.try_wait.parity.acquire.cta.shared::cta.b64 p, [%1], %2, 0x989680;\n\t"
            "selp.b32 %0, 1, 0, p;\n\t}"
            : "=r"(done) : "r"(mbar), "r"(parity) : "memory");
    } while (!done);
}

// ==================================================================================
__global__ __launch_bounds__(TPB, 1) void megakernel(
    const int* __restrict__ idx,
    const float* __restrict__ h0,  const float* __restrict__ c0,
    const float* __restrict__ ctxL, const float* __restrict__ ctxR,
    const float* __restrict__ ctxM, const float* __restrict__ emb,
    const float* __restrict__ Wih0, const float* __restrict__ Whh0,
    const float* __restrict__ bih0, const float* __restrict__ bhh0,
    const float* __restrict__ Wih1, const float* __restrict__ Whh1,
    const float* __restrict__ bih1, const float* __restrict__ bhh1,
    const float* __restrict__ WL, const float* __restrict__ bL,
    const float* __restrict__ WR, const float* __restrict__ bR,
    const float* __restrict__ WM, const float* __restrict__ bM,
    const float* __restrict__ Wc, const float* __restrict__ bc,
    const float* __restrict__ Wo, const float* __restrict__ bo,
    float* __restrict__ out, float* __restrict__ h_new, float* __restrict__ c_new)
{
    __shared__ __align__(16) float sm[5200];
    __shared__ __align__(8) unsigned long long p7bar[NSTAGE];
    extern __shared__ __align__(16) float dyn[];   // 3 x 64KB W_out stages
    const int tid  = threadIdx.x;
    const int wid  = tid >> 5;
    const int lane = tid & 31;
    const int bid  = blockIdx.x;
    const int gw   = bid * 32 + wid;

    // ============ P1: LSTM layer 0 gates + activation (blocks 0..127) ============
    if (bid < 128) {
        const float* x = emb + (size_t)idx[0] * E_SZ;
        for (int i = tid; i < E_SZ; i += TPB) sm[i] = x[i];
        for (int i = tid; i < H_SZ; i += TPB) sm[E_SZ + i] = h0[i];
        __syncthreads();

        const int gi = wid >> 3, jj = wid & 7;
        const int j = bid * 8 + jj;
        const int row = gi * H_SZ + j;
        const float4* a  = (const float4*)(Wih0 + (size_t)row * E_SZ);
        const float4* b  = (const float4*)(Whh0 + (size_t)row * H_SZ);
        const float4* x4 = (const float4*)sm;
        const float4* h4 = (const float4*)(sm + E_SZ);

        float s = 0.f;
        {
            float4 wv[4];
#pragma unroll
            for (int k = 0; k < 4; k++) wv[k] = a[lane + 32 * k];
#pragma unroll
            for (int k = 0; k < 4; k++) s += dot4(wv[k], x4[lane + 32 * k]);
        }
        {
            float4 wv[8];
#pragma unroll
            for (int k = 0; k < 8; k++) wv[k] = b[lane + 32 * k];
#pragma unroll
            for (int k = 0; k < 8; k++) s += dot4(wv[k], h4[lane + 32 * k]);
        }
        s = warp_sum(s);
        if (lane == 0) sm[1536 + gi * 8 + jj] = s + bih0[row] + bhh0[row];
        __syncthreads();

        if (tid < 8) {
            const int jo = bid * 8 + tid;
            const float ig = sigf (sm[1536 + tid]);
            const float fg = sigf (sm[1536 + 8 + tid]);
            const float gg = tanhf(sm[1536 + 16 + tid]);
            const float og = sigf (sm[1536 + 24 + tid]);
            const float c = fg * c0[jo] + ig * gg;
            const float h = og * tanhf(c);
            c_new[jo] = c;
            h_new[jo] = h;
            g_x[jo]  = h;
        }
    }
    gbar();

    // ============ P2: LSTM layer 1 gates + activation, writes q ==================
    if (bid < 128) {
        for (int i = tid; i < H_SZ; i += TPB) sm[i] = g_x[i];
        for (int i = tid; i < H_SZ; i += TPB) sm[H_SZ + i] = h0[H_SZ + i];
        __syncthreads();

        const int gi = wid >> 3, jj = wid & 7;
        const int j = bid * 8 + jj;
        const int row = gi * H_SZ + j;
        const float4* a  = (const float4*)(Wih1 + (size_t)row * H_SZ);
        const float4* b  = (const float4*)(Whh1 + (size_t)row * H_SZ);
        const float4* x4 = (const float4*)sm;
        const float4* h4 = (const float4*)(sm + H_SZ);

        float s = 0.f;
        {
            float4 wv[8];
#pragma unroll
            for (int k = 0; k < 8; k++) wv[k] = a[lane + 32 * k];
#pragma unroll
            for (int k = 0; k < 8; k++) s += dot4(wv[k], x4[lane + 32 * k]);
        }
        {
            float4 wv[8];
#pragma unroll
            for (int k = 0; k < 8; k++) wv[k] = b[lane + 32 * k];
#pragma unroll
            for (int k = 0; k < 8; k++) s += dot4(wv[k], h4[lane + 32 * k]);
        }
        s = warp_sum(s);
        if (lane == 0) sm[2048 + gi * 8 + jj] = s + bih1[row] + bhh1[row];
        __syncthreads();

        if (tid < 8) {
            const int jo = bid * 8 + tid;
            const float ig = sigf (sm[2048 + tid]);
            const float fg = sigf (sm[2048 + 8 + tid]);
            const float gg = tanhf(sm[2048 + 16 + tid]);
            const float og = sigf (sm[2048 + 24 + tid]);
            const float c = fg * c0[H_SZ + jo] + ig * gg;
            const float h = og * tanhf(c);
            c_new[H_SZ + jo] = c;
            h_new[H_SZ + jo] = h;
            g_q[jo] = h;
        }
    }
    gbar();

    // ============ P3: u = W^T q (+ bq) — 192 virtual blocks ======================
    for (int i = tid; i < H_SZ; i += TPB) sm[i] = g_q[i];
    __syncthreads();
    for (int vb = bid; vb < 192; vb += NBLK) {
        const int hd = vb >> 6, chunk = vb & 63;
        const float* W    = (hd == 0) ? WL : (hd == 1) ? WR : WM;
        const float* bias = (hd == 0) ? bL : (hd == 1) ? bR : bM;
        const int col = tid & 3, rgrp = tid >> 2;        // 4 f4 cols, 256 rowgroups
        const int c4 = chunk * 4 + col;
        const float4* W4 = (const float4*)W;

        float4 wv[4];
#pragma unroll
        for (int k = 0; k < 4; k++)
            wv[k] = W4[(size_t)(rgrp + 256 * k) * (C_SZ >> 2) + c4];
        float4 acc = make_float4(0.f, 0.f, 0.f, 0.f);
#pragma unroll
        for (int k = 0; k < 4; k++) {
            float qv = sm[rgrp + 256 * k];
            acc.x += wv[k].x * qv; acc.y += wv[k].y * qv;
            acc.z += wv[k].z * qv; acc.w += wv[k].w * qv;
        }
        float4* red = (float4*)(sm + H_SZ);              // 1024 float4
        red[rgrp * 4 + col] = acc;
        __syncthreads();
#pragma unroll
        for (int sd = 128; sd >= 1; sd >>= 1) {
            if (rgrp < sd) {
                float4 o = red[(rgrp + sd) * 4 + col];
                float4 m = red[rgrp * 4 + col];
                m.x += o.x; m.y += o.y; m.z += o.z; m.w += o.w;
                red[rgrp * 4 + col] = m;
            }
            __syncthreads();
        }
        if (tid < 4) ((float4*)g_u[hd])[chunk * 4 + tid] = red[tid];

        if (chunk == 0) {   // bq = bias . q, fixed-order
            float v = bias[tid] * sm[tid];
            v = warp_sum(v);
            if (lane == 0) sm[5120 + wid] = v;
            __syncthreads();
            if (tid < 32) {
                float t = sm[5120 + tid];
                t = warp_sum(t);
                if (tid == 0) g_bq[hd] = t;
            }
        }
        __syncthreads();
    }
    gbar();

    // ============ P4: e[hd][s] = ctx[s,:]·u[hd] + bq[hd] =========================
    for (int i = tid; i < 3 * C_SZ; i += TPB) sm[i] = ((const float*)g_u)[i];
    __syncthreads();
    for (int r = gw; r < 3 * S_SZ; r += NBLK * 32) {
        const int hd = r >> 11, srow = r & (S_SZ - 1);
        const float* ctx = (hd == 0) ? ctxL : (hd == 1) ? ctxR : ctxM;
        const float4* c4 = (const float4*)(ctx + (size_t)srow * C_SZ);
        const float4* u4 = (const float4*)(sm + hd * C_SZ);
        float4 wv[8];
#pragma unroll
        for (int k = 0; k < 8; k++) wv[k] = c4[lane + 32 * k];
        float s = 0.f;
#pragma unroll
        for (int k = 0; k < 8; k++) s += dot4(wv[k], u4[lane + 32 * k]);
        s = warp_sum(s);
        if (lane == 0) g_e[hd][srow] = s + g_bq[hd];
    }
    gbar();

    // ============ P5: softmax + weighted column-sum partials =====================
    for (int vb = bid; vb < 192; vb += NBLK) {
        const int cc = vb & 7, rc = (vb >> 3) & 7, hd = vb >> 6;
        // softmax stats over full 2048 logits (deterministic)
        const float e0 = g_e[hd][tid], e1 = g_e[hd][tid + 1024];
        float m = warp_max(fmaxf(e0, e1));
        if (lane == 0) sm[4608 + wid] = m;
        __syncthreads();
        if (tid < 32) {
            float v = sm[4608 + tid];
            v = warp_max(v);
            if (tid == 0) sm[4700] = v;
        }
        __syncthreads();
        const float M = sm[4700];
        float z = expf(e0 - M) + expf(e1 - M);
        z = warp_sum(z);
        __syncthreads();
        if (lane == 0) sm[4608 + wid] = z;
        __syncthreads();
        if (tid < 32) {
            float v = sm[4608 + tid];
            v = warp_sum(v);
            if (tid == 0) sm[4701] = v;
        }
        __syncthreads();
        const float inv = 1.0f / sm[4701];
        if (tid < 256) sm[4096 + tid] = expf(g_e[hd][rc * 256 + tid] - M) * inv;
        __syncthreads();

        // weighted column sum over 256 rows (L2-warm from P4)
        const float* ctx = (hd == 0) ? ctxL : (hd == 1) ? ctxR : ctxM;
        const float4* cp = (const float4*)ctx;
        const int c4col = cc * 32 + lane;
        float4 v[8];
#pragma unroll
        for (int k = 0; k < 8; k++)
            v[k] = cp[(size_t)(rc * 256 + wid + 32 * k) * (C_SZ >> 2) + c4col];
        float4 acc = make_float4(0.f, 0.f, 0.f, 0.f);
#pragma unroll
        for (int k = 0; k < 8; k++) {
            float av = sm[4096 + wid + 32 * k];
            acc.x += v[k].x * av; acc.y += v[k].y * av;
            acc.z += v[k].z * av; acc.w += v[k].w * av;
        }
        float4* red4 = (float4*)sm;
        red4[wid * 32 + lane] = acc;
        __syncthreads();
#pragma unroll
        for (int sd = 16; sd >= 1; sd >>= 1) {
            if (wid < sd) {
                float4 o = red4[(wid + sd) * 32 + lane];
                float4 mm = red4[wid * 32 + lane];
                mm.x += o.x; mm.y += o.y; mm.z += o.z; mm.w += o.w;
                red4[wid * 32 + lane] = mm;
            }
            __syncthreads();
        }
        if (wid == 0) ((float4*)g_wpart[hd][rc])[cc * 32 + lane] = red4[lane];
        __syncthreads();
    }
    gbar();

    // ============ P6: concat_out = tanh(Wc @ [q|l|r|m] + bc) (blocks 0..127) =====
    if (bid < 128) {
        for (int i = tid; i < 4 * H_SZ; i += TPB) {
            float v;
            if (i < H_SZ) v = g_q[i];
            else {
                const int hd = (i >> 10) - 1;
                const int c = i & (H_SZ - 1);
                float s = 0.f;
#pragma unroll
                for (int k = 0; k < NRC; k++) s += g_wpart[hd][k][c];
                v = s;
            }
            sm[i] = v;
        }
        __syncthreads();

        const int row = bid * 8 + (wid >> 2);      // 8 rows/block, 4 warps/row
        const int seg = wid & 3;
        const float4* a  = (const float4*)(Wc + (size_t)row * 4 * H_SZ + seg * H_SZ);
        const float4* x4 = (const float4*)(sm + seg * H_SZ);
        float4 wv[8];
#pragma unroll
        for (int k = 0; k < 8; k++) wv[k] = a[lane + 32 * k];
        float s = 0.f;
#pragma unroll
        for (int k = 0; k < 8; k++) s += dot4(wv[k], x4[lane + 32 * k]);
        s = warp_sum(s);
        if (lane == 0) sm[4096 + (wid >> 2) * 4 + seg] = s;
        __syncthreads();
        if (tid < 8) {
            const float t = sm[4096 + tid * 4] + sm[4096 + tid * 4 + 1] +
                            sm[4096 + tid * 4 + 2] + sm[4096 + tid * 4 + 3];
            const int ro = bid * 8 + tid;
            g_co[ro] = tanhf(t + bc[ro]);
        }
    }
    gbar();

    // ============ P7: output = Wo @ concat_out + bo — cp.async.bulk ring =========
    {
        // stage x and init mbarriers
        if (tid < H_SZ) sm[tid] = g_co[tid];
        if (tid == 0) {
#pragma unroll
            for (int s = 0; s < NSTAGE; s++) {
                uint32_t mb = smaddr(&p7bar[s]);
                asm volatile("mbarrier.init.shared.b64 [%0], 1;" :: "r"(mb) : "memory");
            }
            asm volatile("fence.proxy.async.shared::cta;" ::: "memory");
        }
        __syncthreads();

        // warp role: row-in-chunk = wid>>1 (0..15), half = wid&1; x half in regs
        const int rrole = wid >> 1, half = wid & 1;
        const float4* x4 = (const float4*)sm;
        float4 xr[4];
#pragma unroll
        for (int k = 0; k < 4; k++) xr[k] = x4[half * 128 + lane + 32 * k];

        float* part = sm + 1100;          // 32 floats of row partials

        const int base = bid * ROWS_PER_BLK;
        const int rows_total = min(ROWS_PER_BLK, V_SZ - base);
        const int nch = (rows_total + CHUNK_ROWS - 1) / CHUNK_ROWS;
        const char* gbase = (const char*)Wo + (size_t)base * 4096;
        const uint32_t dynb = smaddr(dyn);

        // producer: single bulk copy per chunk (64 KB via TMA engine)
        auto issue = [&](int ch) {
            const int st = ch % NSTAGE;
            const int nrows = min(CHUNK_ROWS, rows_total - ch * CHUNK_ROWS);
            const uint32_t bytes = nrows * 4096;
            const uint32_t mb = smaddr(&p7bar[st]);
            asm volatile("mbarrier.arrive.expect_tx.shared.b64 _, [%0], %1;"
                         :: "r"(mb), "r"(bytes) : "memory");
            asm volatile(
                "cp.async.bulk.shared::cta.global.mbarrier::complete_tx::bytes "
                "[%0], [%1], %2, [%3];"
                :: "r"(dynb + st * CHUNK_BYTES),
                   "l"(gbase + (size_t)ch * CHUNK_BYTES),
                   "r"(bytes), "r"(mb) : "memory");
        };

        if (tid == 0) {
            const int pre = (nch < NSTAGE) ? nch : NSTAGE;
            for (int s = 0; s < pre; s++) issue(s);
        }

        for (int ch = 0; ch < nch; ch++) {
            const int st = ch % NSTAGE;
            mbar_wait(smaddr(&p7bar[st]), (ch / NSTAGE) & 1);

            const int nrows = min(CHUNK_ROWS, rows_total - ch * CHUNK_ROWS);
            if (rrole < nrows) {
                const float4* w4 = (const float4*)(dyn + st * (CHUNK_BYTES / 4));
                const float4* wrow = w4 + rrole * 256 + half * 128;
                float4 wv[4];
#pragma unroll
                for (int k = 0; k < 4; k++) wv[k] = wrow[lane + 32 * k];
                float s = 0.f;
#pragma unroll
                for (int k = 0; k < 4; k++) s += dot4(wv[k], xr[k]);
                s = warp_sum(s);
                if (lane == 0) part[rrole * 2 + half] = s;
            }
            __syncthreads();   // stage fully read + partials visible

            if (tid == 0 && ch + NSTAGE < nch) issue(ch + NSTAGE);

            if (tid < nrows) {
                const int r = base + ch * CHUNK_ROWS + tid;
                out[r] = part[tid * 2] + part[tid * 2 + 1] + bo[r];
            }
        }
    }
}

// ==================================================================================
extern "C" void kernel_launch(void* const* d_in, const int* in_sizes, int n_in,
                              void* d_out, int out_size) {
    const int*   input_ids = (const int*)  d_in[0];
    const float* h0        = (const float*)d_in[1];
    const float* c0        = (const float*)d_in[2];
    const float* ctxL      = (const float*)d_in[3];
    const float* ctxR      = (const float*)d_in[4];
    const float* ctxM      = (const float*)d_in[5];
    const float* emb       = (const float*)d_in[6];
    const float* Wih0      = (const float*)d_in[7];
    const float* Whh0      = (const float*)d_in[8];
    const float* bih0      = (const float*)d_in[9];
    const float* bhh0      = (const float*)d_in[10];
    const float* Wih1      = (const float*)d_in[11];
    const float* Whh1      = (const float*)d_in[12];
    const float* bih1      = (const float*)d_in[13];
    const float* bhh1      = (const float*)d_in[14];
    const float* WL        = (const float*)d_in[15];
    const float* bL        = (const float*)d_in[16];
    const float* WR        = (const float*)d_in[17];
    const float* bR        = (const float*)d_in[18];
    const float* WM        = (const float*)d_in[19];
    const float* bM        = (const float*)d_in[20];
    const float* Wc        = (const float*)d_in[21];
    const float* bc        = (const float*)d_in[22];
    const float* Wo        = (const float*)d_in[23];
    const float* bo        = (const float*)d_in[24];

    float* out   = (float*)d_out;            // [V]
    float* h_new = out + V_SZ;               // [2*H]
    float* c_new = out + V_SZ + 2 * H_SZ;    // [2*H]

    cudaFuncSetAttribute(megakernel,
                         cudaFuncAttributeMaxDynamicSharedMemorySize, DYN_SMEM);

    megakernel<<<NBLK, TPB, DYN_SMEM>>>(
        input_ids, h0, c0, ctxL, ctxR, ctxM, emb,
        Wih0, Whh0, bih0, bhh0, Wih1, Whh1, bih1, bhh1,
        WL, bL, WR, bR, WM, bM, Wc, bc, Wo, bo,
        out, h_new, c_new);
}

// round 14
// speedup vs baseline: 1.0110x; 1.0110x over previous
#include <cuda_runtime.h>
#include <math.h>
#include <stdint.h>

// Shapes
#define V_SZ 50257
#define E_SZ 512
#define H_SZ 1024
#define C_SZ 1024
#define S_SZ 2048
#define NRC 8                // row-chunks for wsum partials
#define NBLK 148             // persistent blocks (1 per SM, single wave)
#define TPB 1024
#define ROWS_PER_BLK 340     // ceil(V_SZ / NBLK)

// P7 hybrid parameters
#define LDG_ROWS 176         // rows served by LDG warps (0-15)
#define TROWS 15             // rows per TMA chunk (one per consumer warp 17-31)
#define NSTAGE 3
#define STAGE_BYTES (TROWS * 4096)           // 60 KB
#define DYN_SMEM (NSTAGE * STAGE_BYTES)      // 180 KB ring

// ---------------- scratch (device globals) --------------------------------------
__device__ __align__(16) float g_x[H_SZ];               // h of layer 0
__device__ __align__(16) float g_q[H_SZ];               // rnn_output
__device__ __align__(16) float g_u[3][C_SZ];            // W^T q per head
__device__            float g_bq[3];                    // b . q per head
__device__ __align__(16) float g_e[3][S_SZ];            // attention logits
__device__ __align__(16) float g_wpart[3][NRC][C_SZ];   // wsum row-chunk partials
__device__ __align__(16) float g_co[H_SZ];              // concat_out

// ---------------- device-wide barrier (sense-reversal, replay-safe) --------------
__device__ unsigned g_barc;
__device__ volatile unsigned g_barg;

__device__ __forceinline__ void gbar() {
    __syncthreads();
    if (threadIdx.x == 0) {
        __threadfence();
        unsigned gen = g_barg;
        if (atomicAdd(&g_barc, 1u) == NBLK - 1) {
            atomicExch(&g_barc, 0u);
            __threadfence();
            g_barg = gen + 1;
        } else {
            while (g_barg == gen) { __nanosleep(64); }
        }
        __threadfence();
    }
    __syncthreads();
}

// ---------------- helpers --------------------------------------------------------
__device__ __forceinline__ float warp_sum(float v) {
#pragma unroll
    for (int o = 16; o; o >>= 1) v += __shfl_xor_sync(0xffffffffu, v, o);
    return v;
}
__device__ __forceinline__ float warp_max(float v) {
#pragma unroll
    for (int o = 16; o; o >>= 1) v = fmaxf(v, __shfl_xor_sync(0xffffffffu, v, o));
    return v;
}
__device__ __forceinline__ float sigf(float x) { return 1.0f / (1.0f + expf(-x)); }
__device__ __forceinline__ float dot4(float4 w, float4 v) {
    return w.x * v.x + w.y * v.y + w.z * v.z + w.w * v.w;
}
__device__ __forceinline__ uint32_t smaddr(const void* p) {
    return (uint32_t)__cvta_generic_to_shared(p);
}
__device__ __forceinline__ void mbar_wait(uint32_t mbar, uint32_t parity) {
    uint32_t done;
    do {
        asm volatile(
            "{\n\t.reg .pred p;\n\t"
            "mbarrier.try_wait.parity.acquire.cta.shared::cta.b64 p, [%1], %2, 0x989680;\n\t"
            "selp.b32 %0, 1, 0, p;\n\t}"
            : "=r"(done) : "r"(mbar), "r"(parity) : "memory");
    } while (!done);
}

// ==================================================================================
__global__ __launch_bounds__(TPB, 1) void megakernel(
    const int* __restrict__ idx,
    const float* __restrict__ h0,  const float* __restrict__ c0,
    const float* __restrict__ ctxL, const float* __restrict__ ctxR,
    const float* __restrict__ ctxM, const float* __restrict__ emb,
    const float* __restrict__ Wih0, const float* __restrict__ Whh0,
    const float* __restrict__ bih0, const float* __restrict__ bhh0,
    const float* __restrict__ Wih1, const float* __restrict__ Whh1,
    const float* __restrict__ bih1, const float* __restrict__ bhh1,
    const float* __restrict__ WL, const float* __restrict__ bL,
    const float* __restrict__ WR, const float* __restrict__ bR,
    const float* __restrict__ WM, const float* __restrict__ bM,
    const float* __restrict__ Wc, const float* __restrict__ bc,
    const float* __restrict__ Wo, const float* __restrict__ bo,
    float* __restrict__ out, float* __restrict__ h_new, float* __restrict__ c_new)
{
    __shared__ __align__(16) float sm[5200];
    __shared__ __align__(8) unsigned long long p7full[NSTAGE];
    __shared__ __align__(8) unsigned long long p7empty[NSTAGE];
    extern __shared__ __align__(16) float dyn[];   // 3 x 60KB TMA stages
    const int tid  = threadIdx.x;
    const int wid  = tid >> 5;
    const int lane = tid & 31;
    const int bid  = blockIdx.x;
    const int gw   = bid * 32 + wid;

    // ---- init P7 mbarriers early (visible by P7 via intervening syncs) ----------
    if (tid == 0) {
#pragma unroll
        for (int s = 0; s < NSTAGE; s++) {
            asm volatile("mbarrier.init.shared.b64 [%0], 1;"
                         :: "r"(smaddr(&p7full[s])) : "memory");
            asm volatile("mbarrier.init.shared.b64 [%0], 15;"
                         :: "r"(smaddr(&p7empty[s])) : "memory");
        }
        asm volatile("fence.proxy.async.shared::cta;" ::: "memory");
    }

    // ============ P1: LSTM layer 0 gates + activation (blocks 0..127) ============
    if (bid < 128) {
        const float* x = emb + (size_t)idx[0] * E_SZ;
        for (int i = tid; i < E_SZ; i += TPB) sm[i] = x[i];
        for (int i = tid; i < H_SZ; i += TPB) sm[E_SZ + i] = h0[i];
        __syncthreads();

        const int gi = wid >> 3, jj = wid & 7;
        const int j = bid * 8 + jj;
        const int row = gi * H_SZ + j;
        const float4* a  = (const float4*)(Wih0 + (size_t)row * E_SZ);
        const float4* b  = (const float4*)(Whh0 + (size_t)row * H_SZ);
        const float4* x4 = (const float4*)sm;
        const float4* h4 = (const float4*)(sm + E_SZ);

        float s = 0.f;
        {
            float4 wv[4];
#pragma unroll
            for (int k = 0; k < 4; k++) wv[k] = a[lane + 32 * k];
#pragma unroll
            for (int k = 0; k < 4; k++) s += dot4(wv[k], x4[lane + 32 * k]);
        }
        {
            float4 wv[8];
#pragma unroll
            for (int k = 0; k < 8; k++) wv[k] = b[lane + 32 * k];
#pragma unroll
            for (int k = 0; k < 8; k++) s += dot4(wv[k], h4[lane + 32 * k]);
        }
        s = warp_sum(s);
        if (lane == 0) sm[1536 + gi * 8 + jj] = s + bih0[row] + bhh0[row];
        __syncthreads();

        if (tid < 8) {
            const int jo = bid * 8 + tid;
            const float ig = sigf (sm[1536 + tid]);
            const float fg = sigf (sm[1536 + 8 + tid]);
            const float gg = tanhf(sm[1536 + 16 + tid]);
            const float og = sigf (sm[1536 + 24 + tid]);
            const float c = fg * c0[jo] + ig * gg;
            const float h = og * tanhf(c);
            c_new[jo] = c;
            h_new[jo] = h;
            g_x[jo]  = h;
        }
    }
    gbar();

    // ============ P2: LSTM layer 1 gates + activation, writes q ==================
    if (bid < 128) {
        for (int i = tid; i < H_SZ; i += TPB) sm[i] = g_x[i];
        for (int i = tid; i < H_SZ; i += TPB) sm[H_SZ + i] = h0[H_SZ + i];
        __syncthreads();

        const int gi = wid >> 3, jj = wid & 7;
        const int j = bid * 8 + jj;
        const int row = gi * H_SZ + j;
        const float4* a  = (const float4*)(Wih1 + (size_t)row * H_SZ);
        const float4* b  = (const float4*)(Whh1 + (size_t)row * H_SZ);
        const float4* x4 = (const float4*)sm;
        const float4* h4 = (const float4*)(sm + H_SZ);

        float s = 0.f;
        {
            float4 wv[8];
#pragma unroll
            for (int k = 0; k < 8; k++) wv[k] = a[lane + 32 * k];
#pragma unroll
            for (int k = 0; k < 8; k++) s += dot4(wv[k], x4[lane + 32 * k]);
        }
        {
            float4 wv[8];
#pragma unroll
            for (int k = 0; k < 8; k++) wv[k] = b[lane + 32 * k];
#pragma unroll
            for (int k = 0; k < 8; k++) s += dot4(wv[k], h4[lane + 32 * k]);
        }
        s = warp_sum(s);
        if (lane == 0) sm[2048 + gi * 8 + jj] = s + bih1[row] + bhh1[row];
        __syncthreads();

        if (tid < 8) {
            const int jo = bid * 8 + tid;
            const float ig = sigf (sm[2048 + tid]);
            const float fg = sigf (sm[2048 + 8 + tid]);
            const float gg = tanhf(sm[2048 + 16 + tid]);
            const float og = sigf (sm[2048 + 24 + tid]);
            const float c = fg * c0[H_SZ + jo] + ig * gg;
            const float h = og * tanhf(c);
            c_new[H_SZ + jo] = c;
            h_new[H_SZ + jo] = h;
            g_q[jo] = h;
        }
    }
    gbar();

    // ============ P3: u = W^T q (+ bq) — 192 virtual blocks ======================
    for (int i = tid; i < H_SZ; i += TPB) sm[i] = g_q[i];
    __syncthreads();
    for (int vb = bid; vb < 192; vb += NBLK) {
        const int hd = vb >> 6, chunk = vb & 63;
        const float* W    = (hd == 0) ? WL : (hd == 1) ? WR : WM;
        const float* bias = (hd == 0) ? bL : (hd == 1) ? bR : bM;
        const int col = tid & 3, rgrp = tid >> 2;        // 4 f4 cols, 256 rowgroups
        const int c4 = chunk * 4 + col;
        const float4* W4 = (const float4*)W;

        float4 wv[4];
#pragma unroll
        for (int k = 0; k < 4; k++)
            wv[k] = W4[(size_t)(rgrp + 256 * k) * (C_SZ >> 2) + c4];
        float4 acc = make_float4(0.f, 0.f, 0.f, 0.f);
#pragma unroll
        for (int k = 0; k < 4; k++) {
            float qv = sm[rgrp + 256 * k];
            acc.x += wv[k].x * qv; acc.y += wv[k].y * qv;
            acc.z += wv[k].z * qv; acc.w += wv[k].w * qv;
        }
        float4* red = (float4*)(sm + H_SZ);              // 1024 float4
        red[rgrp * 4 + col] = acc;
        __syncthreads();
#pragma unroll
        for (int sd = 128; sd >= 1; sd >>= 1) {
            if (rgrp < sd) {
                float4 o = red[(rgrp + sd) * 4 + col];
                float4 m = red[rgrp * 4 + col];
                m.x += o.x; m.y += o.y; m.z += o.z; m.w += o.w;
                red[rgrp * 4 + col] = m;
            }
            __syncthreads();
        }
        if (tid < 4) ((float4*)g_u[hd])[chunk * 4 + tid] = red[tid];

        if (chunk == 0) {   // bq = bias . q, fixed-order
            float v = bias[tid] * sm[tid];
            v = warp_sum(v);
            if (lane == 0) sm[5120 + wid] = v;
            __syncthreads();
            if (tid < 32) {
                float t = sm[5120 + tid];
                t = warp_sum(t);
                if (tid == 0) g_bq[hd] = t;
            }
        }
        __syncthreads();
    }
    gbar();

    // ============ P4: e[hd][s] = ctx[s,:]·u[hd] + bq[hd] =========================
    for (int i = tid; i < 3 * C_SZ; i += TPB) sm[i] = ((const float*)g_u)[i];
    __syncthreads();
    for (int r = gw; r < 3 * S_SZ; r += NBLK * 32) {
        const int hd = r >> 11, srow = r & (S_SZ - 1);
        const float* ctx = (hd == 0) ? ctxL : (hd == 1) ? ctxR : ctxM;
        const float4* c4 = (const float4*)(ctx + (size_t)srow * C_SZ);
        const float4* u4 = (const float4*)(sm + hd * C_SZ);
        float4 wv[8];
#pragma unroll
        for (int k = 0; k < 8; k++) wv[k] = c4[lane + 32 * k];
        float s = 0.f;
#pragma unroll
        for (int k = 0; k < 8; k++) s += dot4(wv[k], u4[lane + 32 * k]);
        s = warp_sum(s);
        if (lane == 0) g_e[hd][srow] = s + g_bq[hd];
    }
    gbar();

    // ============ P5: softmax + weighted column-sum partials =====================
    for (int vb = bid; vb < 192; vb += NBLK) {
        const int cc = vb & 7, rc = (vb >> 3) & 7, hd = vb >> 6;
        // softmax stats over full 2048 logits (deterministic)
        const float e0 = g_e[hd][tid], e1 = g_e[hd][tid + 1024];
        float m = warp_max(fmaxf(e0, e1));
        if (lane == 0) sm[4608 + wid] = m;
        __syncthreads();
        if (tid < 32) {
            float v = sm[4608 + tid];
            v = warp_max(v);
            if (tid == 0) sm[4700] = v;
        }
        __syncthreads();
        const float M = sm[4700];
        float z = expf(e0 - M) + expf(e1 - M);
        z = warp_sum(z);
        __syncthreads();
        if (lane == 0) sm[4608 + wid] = z;
        __syncthreads();
        if (tid < 32) {
            float v = sm[4608 + tid];
            v = warp_sum(v);
            if (tid == 0) sm[4701] = v;
        }
        __syncthreads();
        const float inv = 1.0f / sm[4701];
        if (tid < 256) sm[4096 + tid] = expf(g_e[hd][rc * 256 + tid] - M) * inv;
        __syncthreads();

        // weighted column sum over 256 rows (L2-warm from P4)
        const float* ctx = (hd == 0) ? ctxL : (hd == 1) ? ctxR : ctxM;
        const float4* cp = (const float4*)ctx;
        const int c4col = cc * 32 + lane;
        float4 v[8];
#pragma unroll
        for (int k = 0; k < 8; k++)
            v[k] = cp[(size_t)(rc * 256 + wid + 32 * k) * (C_SZ >> 2) + c4col];
        float4 acc = make_float4(0.f, 0.f, 0.f, 0.f);
#pragma unroll
        for (int k = 0; k < 8; k++) {
            float av = sm[4096 + wid + 32 * k];
            acc.x += v[k].x * av; acc.y += v[k].y * av;
            acc.z += v[k].z * av; acc.w += v[k].w * av;
        }
        float4* red4 = (float4*)sm;
        red4[wid * 32 + lane] = acc;
        __syncthreads();
#pragma unroll
        for (int sd = 16; sd >= 1; sd >>= 1) {
            if (wid < sd) {
                float4 o = red4[(wid + sd) * 32 + lane];
                float4 mm = red4[wid * 32 + lane];
                mm.x += o.x; mm.y += o.y; mm.z += o.z; mm.w += o.w;
                red4[wid * 32 + lane] = mm;
            }
            __syncthreads();
        }
        if (wid == 0) ((float4*)g_wpart[hd][rc])[cc * 32 + lane] = red4[lane];
        __syncthreads();
    }
    gbar();

    // ============ P6: concat_out = tanh(Wc @ [q|l|r|m] + bc) (blocks 0..127) =====
    if (bid < 128) {
        for (int i = tid; i < 4 * H_SZ; i += TPB) {
            float v;
            if (i < H_SZ) v = g_q[i];
            else {
                const int hd = (i >> 10) - 1;
                const int c = i & (H_SZ - 1);
                float s = 0.f;
#pragma unroll
                for (int k = 0; k < NRC; k++) s += g_wpart[hd][k][c];
                v = s;
            }
            sm[i] = v;
        }
        __syncthreads();

        const int row = bid * 8 + (wid >> 2);      // 8 rows/block, 4 warps/row
        const int seg = wid & 3;
        const float4* a  = (const float4*)(Wc + (size_t)row * 4 * H_SZ + seg * H_SZ);
        const float4* x4 = (const float4*)(sm + seg * H_SZ);
        float4 wv[8];
#pragma unroll
        for (int k = 0; k < 8; k++) wv[k] = a[lane + 32 * k];
        float s = 0.f;
#pragma unroll
        for (int k = 0; k < 8; k++) s += dot4(wv[k], x4[lane + 32 * k]);
        s = warp_sum(s);
        if (lane == 0) sm[4096 + (wid >> 2) * 4 + seg] = s;
        __syncthreads();
        if (tid < 8) {
            const float t = sm[4096 + tid * 4] + sm[4096 + tid * 4 + 1] +
                            sm[4096 + tid * 4 + 2] + sm[4096 + tid * 4 + 3];
            const int ro = bid * 8 + tid;
            g_co[ro] = tanhf(t + bc[ro]);
        }
    }
    gbar();

    // ============ P7: hybrid LDG + TMA vocab GEMV ================================
    {
        if (tid < H_SZ) sm[tid] = g_co[tid];
        __syncthreads();                       // last block-wide sync in P7
        const float4* x4 = (const float4*)sm;

        const int base = bid * ROWS_PER_BLK;
        const int rows_total = min(ROWS_PER_BLK, V_SZ - base);
        const int ldg_rows = min(LDG_ROWS, rows_total);
        const int tma_rows = rows_total - ldg_rows;
        const int nch = (tma_rows + TROWS - 1) / TROWS;
        const char* gsrc = (const char*)Wo + (size_t)(base + ldg_rows) * 4096;
        const uint32_t dynb = smaddr(dyn);

        if (wid < 16) {
            // ---- LDG path: 16 warps, proven warp-per-row loop -------------------
            for (int rr = wid; rr < ldg_rows; rr += 16) {
                const int r = base + rr;
                const float4* a = (const float4*)(Wo + (size_t)r * H_SZ);
                float4 wv[8];
#pragma unroll
                for (int k = 0; k < 8; k++) wv[k] = a[lane + 32 * k];
                float s = 0.f;
#pragma unroll
                for (int k = 0; k < 8; k++) s += dot4(wv[k], x4[lane + 32 * k]);
                s = warp_sum(s);
                if (lane == 0) out[r] = s + bo[r];
            }
        } else if (wid == 16) {
            // ---- TMA producer: lane 0 streams chunks into the 3-stage ring ------
            if (lane == 0) {
                for (int ch = 0; ch < nch; ch++) {
                    const int st = ch % NSTAGE;
                    if (ch >= NSTAGE)
                        mbar_wait(smaddr(&p7empty[st]), ((ch - NSTAGE) / NSTAGE) & 1);
                    const int nrows = min(TROWS, tma_rows - ch * TROWS);
                    const uint32_t bytes = nrows * 4096;
                    const uint32_t mb = smaddr(&p7full[st]);
                    asm volatile("mbarrier.arrive.expect_tx.shared.b64 _, [%0], %1;"
                                 :: "r"(mb), "r"(bytes) : "memory");
                    asm volatile(
                        "cp.async.bulk.shared::cta.global.mbarrier::complete_tx::bytes "
                        "[%0], [%1], %2, [%3];"
                        :: "r"(dynb + st * STAGE_BYTES),
                           "l"(gsrc + (size_t)ch * TROWS * 4096),
                           "r"(bytes), "r"(mb) : "memory");
                }
            }
        } else {
            // ---- TMA consumers: warps 17-31, one row per chunk each -------------
            const int cw = wid - 17;           // 0..14
            for (int ch = 0; ch < nch; ch++) {
                const int st = ch % NSTAGE;
                mbar_wait(smaddr(&p7full[st]), (ch / NSTAGE) & 1);
                const int nrows = min(TROWS, tma_rows - ch * TROWS);
                if (cw < nrows) {
                    const float4* wrow =
                        (const float4*)(dyn + (size_t)st * (STAGE_BYTES / 4)) + cw * 256;
                    float4 wv[8];
#pragma unroll
                    for (int k = 0; k < 8; k++) wv[k] = wrow[lane + 32 * k];
                    float s = 0.f;
#pragma unroll
                    for (int k = 0; k < 8; k++) s += dot4(wv[k], x4[lane + 32 * k]);
                    s = warp_sum(s);
                    if (lane == 0) {
                        const int r = base + ldg_rows + ch * TROWS + cw;
                        out[r] = s + bo[r];
                    }
                }
                __syncwarp();
                if (lane == 0)
                    asm volatile("mbarrier.arrive.shared.b64 _, [%0];"
                                 :: "r"(smaddr(&p7empty[st])) : "memory");
            }
        }
    }
}

// ==================================================================================
extern "C" void kernel_launch(void* const* d_in, const int* in_sizes, int n_in,
                              void* d_out, int out_size) {
    const int*   input_ids = (const int*)  d_in[0];
    const float* h0        = (const float*)d_in[1];
    const float* c0        = (const float*)d_in[2];
    const float* ctxL      = (const float*)d_in[3];
    const float* ctxR      = (const float*)d_in[4];
    const float* ctxM      = (const float*)d_in[5];
    const float* emb       = (const float*)d_in[6];
    const float* Wih0      = (const float*)d_in[7];
    const float* Whh0      = (const float*)d_in[8];
    const float* bih0      = (const float*)d_in[9];
    const float* bhh0      = (const float*)d_in[10];
    const float* Wih1      = (const float*)d_in[11];
    const float* Whh1      = (const float*)d_in[12];
    const float* bih1      = (const float*)d_in[13];
    const float* bhh1      = (const float*)d_in[14];
    const float* WL        = (const float*)d_in[15];
    const float* bL        = (const float*)d_in[16];
    const float* WR        = (const float*)d_in[17];
    const float* bR        = (const float*)d_in[18];
    const float* WM        = (const float*)d_in[19];
    const float* bM        = (const float*)d_in[20];
    const float* Wc        = (const float*)d_in[21];
    const float* bc        = (const float*)d_in[22];
    const float* Wo        = (const float*)d_in[23];
    const float* bo        = (const float*)d_in[24];

    float* out   = (float*)d_out;            // [V]
    float* h_new = out + V_SZ;               // [2*H]
    float* c_new = out + V_SZ + 2 * H_SZ;    // [2*H]

    cudaFuncSetAttribute(megakernel,
                         cudaFuncAttributeMaxDynamicSharedMemorySize, DYN_SMEM);

    megakernel<<<NBLK, TPB, DYN_SMEM>>>(
        input_ids, h0, c0, ctxL, ctxR, ctxM, emb,
        Wih0, Whh0, bih0, bhh0, Wih1, Whh1, bih1, bhh1,
        WL, bL, WR, bR, WM, bM, Wc, bc, Wo, bo,
        out, h_new, c_new);
}

// round 15
// speedup vs baseline: 1.0366x; 1.0254x over previous
#include <cuda_runtime.h>
#include <math.h>

// Shapes
#define V_SZ 50257
#define E_SZ 512
#define H_SZ 1024
#define C_SZ 1024
#define S_SZ 2048
#define NRC 8                // row-chunks for wsum partials
#define NBLK 148             // persistent blocks (1 per SM, single wave)
#define TPB 1024
#define ROWS_PER_BLK 340     // ceil(V_SZ / NBLK)
#define PF_LINES 4096        // 512 KB budget of W_out per block (own P7 slice)

// ---------------- scratch (device globals) --------------------------------------
__device__ __align__(16) float g_x[H_SZ];               // h of layer 0
__device__ __align__(16) float g_q[H_SZ];               // rnn_output
__device__ __align__(16) float g_u[3][C_SZ];            // W^T q per head
__device__            float g_bq[3];                    // b . q per head
__device__ __align__(16) float g_e[3][S_SZ];            // attention logits
__device__ __align__(16) float g_wpart[3][NRC][C_SZ];   // wsum row-chunk partials
__device__ __align__(16) float g_co[H_SZ];              // concat_out

// ---------------- device-wide barrier (sense-reversal, replay-safe) --------------
__device__ unsigned g_barc;
__device__ volatile unsigned g_barg;

__device__ __forceinline__ void gbar() {
    __syncthreads();
    if (threadIdx.x == 0) {
        __threadfence();
        unsigned gen = g_barg;
        if (atomicAdd(&g_barc, 1u) == NBLK - 1) {
            atomicExch(&g_barc, 0u);
            __threadfence();
            g_barg = gen + 1;
        } else {
            while (g_barg == gen) { __nanosleep(64); }
        }
        __threadfence();
    }
    __syncthreads();
}

// Barrier variant: while waiting, warp 1 prefetches this block's P7 slice of
// W_out into L2 (evict_last). Used ONLY after P1/P2/P3 so ctx residency for
// P4/P5 is never disturbed.
__device__ __forceinline__ void gbar_pf(const char* pf_base, int& pf_i) {
    __shared__ int s_rel;
    __syncthreads();
    if (threadIdx.x == 0) s_rel = 0;
    __syncthreads();
    const int tid = threadIdx.x;
    if (tid == 0) {
        __threadfence();
        unsigned gen = g_barg;
        if (atomicAdd(&g_barc, 1u) == NBLK - 1) {
            atomicExch(&g_barc, 0u);
            __threadfence();
            g_barg = gen + 1;
        } else {
            while (g_barg == gen) { __nanosleep(64); }
        }
        __threadfence();
        *(volatile int*)&s_rel = 1;
    } else if (tid >= 32 && tid < 64) {
        const int ln = tid - 32;
        while (*(volatile int*)&s_rel == 0) {
            if (pf_i < PF_LINES) {
                const char* p = pf_base + (size_t)(pf_i + ln) * 128;
#pragma unroll
                for (int k = 0; k < 4; k++)
                    asm volatile("prefetch.global.L2::evict_last [%0];" :: "l"(p + k * 4096));
                pf_i += 128;          // 16 KB per iteration
            }
            __nanosleep(256);
        }
    }
    __syncthreads();
}

// ---------------- helpers --------------------------------------------------------
__device__ __forceinline__ float warp_sum(float v) {
#pragma unroll
    for (int o = 16; o; o >>= 1) v += __shfl_xor_sync(0xffffffffu, v, o);
    return v;
}
__device__ __forceinline__ float warp_max(float v) {
#pragma unroll
    for (int o = 16; o; o >>= 1) v = fmaxf(v, __shfl_xor_sync(0xffffffffu, v, o));
    return v;
}
__device__ __forceinline__ float sigf(float x) { return 1.0f / (1.0f + expf(-x)); }
__device__ __forceinline__ float dot4(float4 w, float4 v) {
    return w.x * v.x + w.y * v.y + w.z * v.z + w.w * v.w;
}

// ==================================================================================
__global__ __launch_bounds__(TPB, 1) void megakernel(
    const int* __restrict__ idx,
    const float* __restrict__ h0,  const float* __restrict__ c0,
    const float* __restrict__ ctxL, const float* __restrict__ ctxR,
    const float* __restrict__ ctxM, const float* __restrict__ emb,
    const float* __restrict__ Wih0, const float* __restrict__ Whh0,
    const float* __restrict__ bih0, const float* __restrict__ bhh0,
    const float* __restrict__ Wih1, const float* __restrict__ Whh1,
    const float* __restrict__ bih1, const float* __restrict__ bhh1,
    const float* __restrict__ WL, const float* __restrict__ bL,
    const float* __restrict__ WR, const float* __restrict__ bR,
    const float* __restrict__ WM, const float* __restrict__ bM,
    const float* __restrict__ Wc, const float* __restrict__ bc,
    const float* __restrict__ Wo, const float* __restrict__ bo,
    float* __restrict__ out, float* __restrict__ h_new, float* __restrict__ c_new)
{
    __shared__ __align__(16) float sm[5200];
    const int tid  = threadIdx.x;
    const int wid  = tid >> 5;
    const int lane = tid & 31;
    const int bid  = blockIdx.x;
    const int gw   = bid * 32 + wid;

    // this block's own P7 slice of W_out (prefetch target)
    const char* pf_base = (const char*)Wo + (size_t)bid * ROWS_PER_BLK * 4096;
    int pf_i = 3072;     // barrier prefetcher continues after the 3 bursts

    // ---- prefetch burst 0 (128 KB, 1 line/thread, fire-and-forget) --------------
    asm volatile("prefetch.global.L2::evict_last [%0];"
                 :: "l"(pf_base + (size_t)tid * 128));

    // ============ P1: LSTM layer 0 gates + activation (blocks 0..127) ============
    if (bid < 128) {
        const float* x = emb + (size_t)idx[0] * E_SZ;
        for (int i = tid; i < E_SZ; i += TPB) sm[i] = x[i];
        for (int i = tid; i < H_SZ; i += TPB) sm[E_SZ + i] = h0[i];
        __syncthreads();

        const int gi = wid >> 3, jj = wid & 7;
        const int j = bid * 8 + jj;
        const int row = gi * H_SZ + j;
        const float4* a  = (const float4*)(Wih0 + (size_t)row * E_SZ);
        const float4* b  = (const float4*)(Whh0 + (size_t)row * H_SZ);
        const float4* x4 = (const float4*)sm;
        const float4* h4 = (const float4*)(sm + E_SZ);

        float s = 0.f;
        {
            float4 wv[4];
#pragma unroll
            for (int k = 0; k < 4; k++) wv[k] = a[lane + 32 * k];
#pragma unroll
            for (int k = 0; k < 4; k++) s += dot4(wv[k], x4[lane + 32 * k]);
        }
        {
            float4 wv[8];
#pragma unroll
            for (int k = 0; k < 8; k++) wv[k] = b[lane + 32 * k];
#pragma unroll
            for (int k = 0; k < 8; k++) s += dot4(wv[k], h4[lane + 32 * k]);
        }
        s = warp_sum(s);
        if (lane == 0) sm[1536 + gi * 8 + jj] = s + bih0[row] + bhh0[row];
        __syncthreads();

        if (tid < 8) {
            const int jo = bid * 8 + tid;
            const float ig = sigf (sm[1536 + tid]);
            const float fg = sigf (sm[1536 + 8 + tid]);
            const float gg = tanhf(sm[1536 + 16 + tid]);
            const float og = sigf (sm[1536 + 24 + tid]);
            const float c = fg * c0[jo] + ig * gg;
            const float h = og * tanhf(c);
            c_new[jo] = c;
            h_new[jo] = h;
            g_x[jo]  = h;
        }
    }
    gbar_pf(pf_base, pf_i);

    // ---- prefetch burst 1 --------------------------------------------------------
    asm volatile("prefetch.global.L2::evict_last [%0];"
                 :: "l"(pf_base + (size_t)(1024 + tid) * 128));

    // ============ P2: LSTM layer 1 gates + activation, writes q ==================
    if (bid < 128) {
        for (int i = tid; i < H_SZ; i += TPB) sm[i] = g_x[i];
        for (int i = tid; i < H_SZ; i += TPB) sm[H_SZ + i] = h0[H_SZ + i];
        __syncthreads();

        const int gi = wid >> 3, jj = wid & 7;
        const int j = bid * 8 + jj;
        const int row = gi * H_SZ + j;
        const float4* a  = (const float4*)(Wih1 + (size_t)row * H_SZ);
        const float4* b  = (const float4*)(Whh1 + (size_t)row * H_SZ);
        const float4* x4 = (const float4*)sm;
        const float4* h4 = (const float4*)(sm + H_SZ);

        float s = 0.f;
        {
            float4 wv[8];
#pragma unroll
            for (int k = 0; k < 8; k++) wv[k] = a[lane + 32 * k];
#pragma unroll
            for (int k = 0; k < 8; k++) s += dot4(wv[k], x4[lane + 32 * k]);
        }
        {
            float4 wv[8];
#pragma unroll
            for (int k = 0; k < 8; k++) wv[k] = b[lane + 32 * k];
#pragma unroll
            for (int k = 0; k < 8; k++) s += dot4(wv[k], h4[lane + 32 * k]);
        }
        s = warp_sum(s);
        if (lane == 0) sm[2048 + gi * 8 + jj] = s + bih1[row] + bhh1[row];
        __syncthreads();

        if (tid < 8) {
            const int jo = bid * 8 + tid;
            const float ig = sigf (sm[2048 + tid]);
            const float fg = sigf (sm[2048 + 8 + tid]);
            const float gg = tanhf(sm[2048 + 16 + tid]);
            const float og = sigf (sm[2048 + 24 + tid]);
            const float c = fg * c0[H_SZ + jo] + ig * gg;
            const float h = og * tanhf(c);
            c_new[H_SZ + jo] = c;
            h_new[H_SZ + jo] = h;
            g_q[jo] = h;
        }
    }
    gbar_pf(pf_base, pf_i);

    // ---- prefetch burst 2 --------------------------------------------------------
    asm volatile("prefetch.global.L2::evict_last [%0];"
                 :: "l"(pf_base + (size_t)(2048 + tid) * 128));

    // ============ P3: u = W^T q (+ bq) — 192 virtual blocks ======================
    for (int i = tid; i < H_SZ; i += TPB) sm[i] = g_q[i];
    __syncthreads();
    for (int vb = bid; vb < 192; vb += NBLK) {
        const int hd = vb >> 6, chunk = vb & 63;
        const float* W    = (hd == 0) ? WL : (hd == 1) ? WR : WM;
        const float* bias = (hd == 0) ? bL : (hd == 1) ? bR : bM;
        const int col = tid & 3, rgrp = tid >> 2;        // 4 f4 cols, 256 rowgroups
        const int c4 = chunk * 4 + col;
        const float4* W4 = (const float4*)W;

        float4 wv[4];
#pragma unroll
        for (int k = 0; k < 4; k++)
            wv[k] = W4[(size_t)(rgrp + 256 * k) * (C_SZ >> 2) + c4];
        float4 acc = make_float4(0.f, 0.f, 0.f, 0.f);
#pragma unroll
        for (int k = 0; k < 4; k++) {
            float qv = sm[rgrp + 256 * k];
            acc.x += wv[k].x * qv; acc.y += wv[k].y * qv;
            acc.z += wv[k].z * qv; acc.w += wv[k].w * qv;
        }
        float4* red = (float4*)(sm + H_SZ);              // 1024 float4
        red[rgrp * 4 + col] = acc;
        __syncthreads();
#pragma unroll
        for (int sd = 128; sd >= 1; sd >>= 1) {
            if (rgrp < sd) {
                float4 o = red[(rgrp + sd) * 4 + col];
                float4 m = red[rgrp * 4 + col];
                m.x += o.x; m.y += o.y; m.z += o.z; m.w += o.w;
                red[rgrp * 4 + col] = m;
            }
            __syncthreads();
        }
        if (tid < 4) ((float4*)g_u[hd])[chunk * 4 + tid] = red[tid];

        if (chunk == 0) {   // bq = bias . q, fixed-order
            float v = bias[tid] * sm[tid];
            v = warp_sum(v);
            if (lane == 0) sm[5120 + wid] = v;
            __syncthreads();
            if (tid < 32) {
                float t = sm[5120 + tid];
                t = warp_sum(t);
                if (tid == 0) g_bq[hd] = t;
            }
        }
        __syncthreads();
    }
    gbar_pf(pf_base, pf_i);

    // ============ P4: e[hd][s] = ctx[s,:]·u[hd] + bq[hd] =========================
    for (int i = tid; i < 3 * C_SZ; i += TPB) sm[i] = ((const float*)g_u)[i];
    __syncthreads();
    for (int r = gw; r < 3 * S_SZ; r += NBLK * 32) {
        const int hd = r >> 11, srow = r & (S_SZ - 1);
        const float* ctx = (hd == 0) ? ctxL : (hd == 1) ? ctxR : ctxM;
        const float4* c4 = (const float4*)(ctx + (size_t)srow * C_SZ);
        const float4* u4 = (const float4*)(sm + hd * C_SZ);
        float4 wv[8];
#pragma unroll
        for (int k = 0; k < 8; k++) wv[k] = c4[lane + 32 * k];
        float s = 0.f;
#pragma unroll
        for (int k = 0; k < 8; k++) s += dot4(wv[k], u4[lane + 32 * k]);
        s = warp_sum(s);
        if (lane == 0) g_e[hd][srow] = s + g_bq[hd];
    }
    gbar();

    // ============ P5: softmax + weighted column-sum partials =====================
    for (int vb = bid; vb < 192; vb += NBLK) {
        const int cc = vb & 7, rc = (vb >> 3) & 7, hd = vb >> 6;
        // softmax stats over full 2048 logits (deterministic)
        const float e0 = g_e[hd][tid], e1 = g_e[hd][tid + 1024];
        float m = warp_max(fmaxf(e0, e1));
        if (lane == 0) sm[4608 + wid] = m;
        __syncthreads();
        if (tid < 32) {
            float v = sm[4608 + tid];
            v = warp_max(v);
            if (tid == 0) sm[4700] = v;
        }
        __syncthreads();
        const float M = sm[4700];
        float z = expf(e0 - M) + expf(e1 - M);
        z = warp_sum(z);
        __syncthreads();
        if (lane == 0) sm[4608 + wid] = z;
        __syncthreads();
        if (tid < 32) {
            float v = sm[4608 + tid];
            v = warp_sum(v);
            if (tid == 0) sm[4701] = v;
        }
        __syncthreads();
        const float inv = 1.0f / sm[4701];
        if (tid < 256) sm[4096 + tid] = expf(g_e[hd][rc * 256 + tid] - M) * inv;
        __syncthreads();

        // weighted column sum over 256 rows (L2-warm from P4)
        const float* ctx = (hd == 0) ? ctxL : (hd == 1) ? ctxR : ctxM;
        const float4* cp = (const float4*)ctx;
        const int c4col = cc * 32 + lane;
        float4 v[8];
#pragma unroll
        for (int k = 0; k < 8; k++)
            v[k] = cp[(size_t)(rc * 256 + wid + 32 * k) * (C_SZ >> 2) + c4col];
        float4 acc = make_float4(0.f, 0.f, 0.f, 0.f);
#pragma unroll
        for (int k = 0; k < 8; k++) {
            float av = sm[4096 + wid + 32 * k];
            acc.x += v[k].x * av; acc.y += v[k].y * av;
            acc.z += v[k].z * av; acc.w += v[k].w * av;
        }
        float4* red4 = (float4*)sm;
        red4[wid * 32 + lane] = acc;
        __syncthreads();
#pragma unroll
        for (int sd = 16; sd >= 1; sd >>= 1) {
            if (wid < sd) {
                float4 o = red4[(wid + sd) * 32 + lane];
                float4 mm = red4[wid * 32 + lane];
                mm.x += o.x; mm.y += o.y; mm.z += o.z; mm.w += o.w;
                red4[wid * 32 + lane] = mm;
            }
            __syncthreads();
        }
        if (wid == 0) ((float4*)g_wpart[hd][rc])[cc * 32 + lane] = red4[lane];
        __syncthreads();
    }
    gbar();

    // ============ P6: concat_out = tanh(Wc @ [q|l|r|m] + bc) (blocks 0..127) =====
    if (bid < 128) {
        for (int i = tid; i < 4 * H_SZ; i += TPB) {
            float v;
            if (i < H_SZ) v = g_q[i];
            else {
                const int hd = (i >> 10) - 1;
                const int c = i & (H_SZ - 1);
                float s = 0.f;
#pragma unroll
                for (int k = 0; k < NRC; k++) s += g_wpart[hd][k][c];
                v = s;
            }
            sm[i] = v;
        }
        __syncthreads();

        const int row = bid * 8 + (wid >> 2);      // 8 rows/block, 4 warps/row
        const int seg = wid & 3;
        const float4* a  = (const float4*)(Wc + (size_t)row * 4 * H_SZ + seg * H_SZ);
        const float4* x4 = (const float4*)(sm + seg * H_SZ);
        float4 wv[8];
#pragma unroll
        for (int k = 0; k < 8; k++) wv[k] = a[lane + 32 * k];
        float s = 0.f;
#pragma unroll
        for (int k = 0; k < 8; k++) s += dot4(wv[k], x4[lane + 32 * k]);
        s = warp_sum(s);
        if (lane == 0) sm[4096 + (wid >> 2) * 4 + seg] = s;
        __syncthreads();
        if (tid < 8) {
            const float t = sm[4096 + tid * 4] + sm[4096 + tid * 4 + 1] +
                            sm[4096 + tid * 4 + 2] + sm[4096 + tid * 4 + 3];
            const int ro = bid * 8 + tid;
            g_co[ro] = tanhf(t + bc[ro]);
        }
    }
    gbar();

    // ============ P7: output = Wo @ concat_out + bo (R6 structure) ===============
    // Block reads its own contiguous slice first-ish: warps stride the whole
    // vocab range as in R6 — prefetched region (own slice head) gets L2 hits.
    if (tid < H_SZ) sm[tid] = g_co[tid];
    __syncthreads();
    const float4* x4 = (const float4*)sm;
    // remap: block covers rows [bid*340, ...) first so prefetched lines hit
    const int base = bid * ROWS_PER_BLK;
    for (int rr = wid; rr < ROWS_PER_BLK; rr += 32) {
        const int r = base + rr;
        if (r >= V_SZ) break;
        const float4* a = (const float4*)(Wo + (size_t)r * H_SZ);
        float4 wv[8];
#pragma unroll
        for (int k = 0; k < 8; k++) wv[k] = a[lane + 32 * k];
        float s = 0.f;
#pragma unroll
        for (int k = 0; k < 8; k++) s += dot4(wv[k], x4[lane + 32 * k]);
        s = warp_sum(s);
        if (lane == 0) out[r] = s + bo[r];
    }
}

// ==================================================================================
extern "C" void kernel_launch(void* const* d_in, const int* in_sizes, int n_in,
                              void* d_out, int out_size) {
    const int*   input_ids = (const int*)  d_in[0];
    const float* h0        = (const float*)d_in[1];
    const float* c0        = (const float*)d_in[2];
    const float* ctxL      = (const float*)d_in[3];
    const float* ctxR      = (const float*)d_in[4];
    const float* ctxM      = (const float*)d_in[5];
    const float* emb       = (const float*)d_in[6];
    const float* Wih0      = (const float*)d_in[7];
    const float* Whh0      = (const float*)d_in[8];
    const float* bih0      = (const float*)d_in[9];
    const float* bhh0      = (const float*)d_in[10];
    const float* Wih1      = (const float*)d_in[11];
    const float* Whh1      = (const float*)d_in[12];
    const float* bih1      = (const float*)d_in[13];
    const float* bhh1      = (const float*)d_in[14];
    const float* WL        = (const float*)d_in[15];
    const float* bL        = (const float*)d_in[16];
    const float* WR        = (const float*)d_in[17];
    const float* bR        = (const float*)d_in[18];
    const float* WM        = (const float*)d_in[19];
    const float* bM        = (const float*)d_in[20];
    const float* Wc        = (const float*)d_in[21];
    const float* bc        = (const float*)d_in[22];
    const float* Wo        = (const float*)d_in[23];
    const float* bo        = (const float*)d_in[24];

    float* out   = (float*)d_out;            // [V]
    float* h_new = out + V_SZ;               // [2*H]
    float* c_new = out + V_SZ + 2 * H_SZ;    // [2*H]

    megakernel<<<NBLK, TPB>>>(input_ids, h0, c0, ctxL, ctxR, ctxM, emb,
                              Wih0, Whh0, bih0, bhh0, Wih1, Whh1, bih1, bhh1,
                              WL, bL, WR, bR, WM, bM, Wc, bc, Wo, bo,
                              out, h_new, c_new);
}

// round 16
// speedup vs baseline: 1.1381x; 1.0979x over previous
#include <cuda_runtime.h>
#include <math.h>

// Shapes
#define V_SZ 50257
#define E_SZ 512
#define H_SZ 1024
#define C_SZ 1024
#define S_SZ 2048
#define NRC 8                // row-chunks for wsum partials
#define NBLK 148             // persistent blocks (<= SM count, 1 per SM)
#define TPB 1024

// ---------------- scratch (device globals) --------------------------------------
__device__ __align__(16) float g_x[H_SZ];               // h of layer 0 (input to layer 1)
__device__ __align__(16) float g_q[H_SZ];               // rnn_output
__device__ __align__(16) float g_u[3][C_SZ];            // W^T q per head
__device__            float g_bq[3];                    // b . q per head
__device__ __align__(16) float g_e[3][S_SZ];            // attention logits
__device__ __align__(16) float g_wpart[3][NRC][C_SZ];   // wsum row-chunk partials
__device__ __align__(16) float g_co[H_SZ];              // concat_out

// ---------------- device-wide barrier (sense-reversal, replay-safe) --------------
__device__ unsigned g_barc;                 // arrival counter (reset each use)
__device__ volatile unsigned g_barg;        // generation (monotonic across replays)

__device__ __forceinline__ void gbar() {
    __syncthreads();
    if (threadIdx.x == 0) {
        __threadfence();                    // publish this block's writes
        unsigned gen = g_barg;
        if (atomicAdd(&g_barc, 1u) == NBLK - 1) {
            atomicExch(&g_barc, 0u);        // reset BEFORE releasing
            __threadfence();
            g_barg = gen + 1;               // release
        } else {
            while (g_barg == gen) { __nanosleep(64); }
        }
        __threadfence();                    // acquire
    }
    __syncthreads();
}

// ---------------- helpers --------------------------------------------------------
__device__ __forceinline__ float warp_sum(float v) {
#pragma unroll
    for (int o = 16; o; o >>= 1) v += __shfl_xor_sync(0xffffffffu, v, o);
    return v;
}
__device__ __forceinline__ float warp_max(float v) {
#pragma unroll
    for (int o = 16; o; o >>= 1) v = fmaxf(v, __shfl_xor_sync(0xffffffffu, v, o));
    return v;
}
__device__ __forceinline__ float sigf(float x) { return 1.0f / (1.0f + expf(-x)); }
__device__ __forceinline__ float dot4(float4 w, float4 v) {
    return w.x * v.x + w.y * v.y + w.z * v.z + w.w * v.w;
}

// ==================================================================================
__global__ __launch_bounds__(TPB, 1) void megakernel(
    const int* __restrict__ idx,
    const float* __restrict__ h0,  const float* __restrict__ c0,
    const float* __restrict__ ctxL, const float* __restrict__ ctxR,
    const float* __restrict__ ctxM, const float* __restrict__ emb,
    const float* __restrict__ Wih0, const float* __restrict__ Whh0,
    const float* __restrict__ bih0, const float* __restrict__ bhh0,
    const float* __restrict__ Wih1, const float* __restrict__ Whh1,
    const float* __restrict__ bih1, const float* __restrict__ bhh1,
    const float* __restrict__ WL, const float* __restrict__ bL,
    const float* __restrict__ WR, const float* __restrict__ bR,
    const float* __restrict__ WM, const float* __restrict__ bM,
    const float* __restrict__ Wc, const float* __restrict__ bc,
    const float* __restrict__ Wo, const float* __restrict__ bo,
    float* __restrict__ out, float* __restrict__ h_new, float* __restrict__ c_new)
{
    __shared__ __align__(16) float sm[5200];
    const int tid  = threadIdx.x;
    const int wid  = tid >> 5;
    const int lane = tid & 31;
    const int bid  = blockIdx.x;
    const int gw   = bid * 32 + wid;

    // ============ P1: LSTM layer 0 gates + activation (blocks 0..127) ============
    if (bid < 128) {
        const float* x = emb + (size_t)idx[0] * E_SZ;
        for (int i = tid; i < E_SZ; i += TPB) sm[i] = x[i];
        for (int i = tid; i < H_SZ; i += TPB) sm[E_SZ + i] = h0[i];
        __syncthreads();

        const int gi = wid >> 3, jj = wid & 7;
        const int j = bid * 8 + jj;
        const int row = gi * H_SZ + j;
        const float4* a  = (const float4*)(Wih0 + (size_t)row * E_SZ);
        const float4* b  = (const float4*)(Whh0 + (size_t)row * H_SZ);
        const float4* x4 = (const float4*)sm;
        const float4* h4 = (const float4*)(sm + E_SZ);

        float s = 0.f;
        {   // x part: 128 f4, 4 per lane
            float4 wv[4];
#pragma unroll
            for (int k = 0; k < 4; k++) wv[k] = a[lane + 32 * k];
#pragma unroll
            for (int k = 0; k < 4; k++) s += dot4(wv[k], x4[lane + 32 * k]);
        }
        {   // h part: 256 f4, 8 per lane
            float4 wv[8];
#pragma unroll
            for (int k = 0; k < 8; k++) wv[k] = b[lane + 32 * k];
#pragma unroll
            for (int k = 0; k < 8; k++) s += dot4(wv[k], h4[lane + 32 * k]);
        }
        s = warp_sum(s);
        if (lane == 0) sm[1536 + gi * 8 + jj] = s + bih0[row] + bhh0[row];
        __syncthreads();

        if (tid < 8) {
            const int jo = bid * 8 + tid;
            const float ig = sigf (sm[1536 + tid]);
            const float fg = sigf (sm[1536 + 8 + tid]);
            const float gg = tanhf(sm[1536 + 16 + tid]);
            const float og = sigf (sm[1536 + 24 + tid]);
            const float c = fg * c0[jo] + ig * gg;
            const float h = og * tanhf(c);
            c_new[jo] = c;
            h_new[jo] = h;
            g_x[jo]  = h;
        }
    }
    gbar();

    // ============ P2: LSTM layer 1 gates + activation, writes q ==================
    if (bid < 128) {
        for (int i = tid; i < H_SZ; i += TPB) sm[i] = g_x[i];
        for (int i = tid; i < H_SZ; i += TPB) sm[H_SZ + i] = h0[H_SZ + i];
        __syncthreads();

        const int gi = wid >> 3, jj = wid & 7;
        const int j = bid * 8 + jj;
        const int row = gi * H_SZ + j;
        const float4* a  = (const float4*)(Wih1 + (size_t)row * H_SZ);
        const float4* b  = (const float4*)(Whh1 + (size_t)row * H_SZ);
        const float4* x4 = (const float4*)sm;
        const float4* h4 = (const float4*)(sm + H_SZ);

        float s = 0.f;
        {
            float4 wv[8];
#pragma unroll
            for (int k = 0; k < 8; k++) wv[k] = a[lane + 32 * k];
#pragma unroll
            for (int k = 0; k < 8; k++) s += dot4(wv[k], x4[lane + 32 * k]);
        }
        {
            float4 wv[8];
#pragma unroll
            for (int k = 0; k < 8; k++) wv[k] = b[lane + 32 * k];
#pragma unroll
            for (int k = 0; k < 8; k++) s += dot4(wv[k], h4[lane + 32 * k]);
        }
        s = warp_sum(s);
        if (lane == 0) sm[2048 + gi * 8 + jj] = s + bih1[row] + bhh1[row];
        __syncthreads();

        if (tid < 8) {
            const int jo = bid * 8 + tid;
            const float ig = sigf (sm[2048 + tid]);
            const float fg = sigf (sm[2048 + 8 + tid]);
            const float gg = tanhf(sm[2048 + 16 + tid]);
            const float og = sigf (sm[2048 + 24 + tid]);
            const float c = fg * c0[H_SZ + jo] + ig * gg;
            const float h = og * tanhf(c);
            c_new[H_SZ + jo] = c;
            h_new[H_SZ + jo] = h;
            g_q[jo] = h;
        }
    }
    gbar();

    // ============ P3: u = W^T q (+ bq) — 192 virtual blocks ======================
    for (int i = tid; i < H_SZ; i += TPB) sm[i] = g_q[i];
    __syncthreads();
    for (int vb = bid; vb < 192; vb += NBLK) {
        const int hd = vb >> 6, chunk = vb & 63;
        const float* W    = (hd == 0) ? WL : (hd == 1) ? WR : WM;
        const float* bias = (hd == 0) ? bL : (hd == 1) ? bR : bM;
        const int col = tid & 3, rgrp = tid >> 2;        // 4 f4 cols, 256 rowgroups
        const int c4 = chunk * 4 + col;
        const float4* W4 = (const float4*)W;

        float4 wv[4];
#pragma unroll
        for (int k = 0; k < 4; k++)
            wv[k] = W4[(size_t)(rgrp + 256 * k) * (C_SZ >> 2) + c4];
        float4 acc = make_float4(0.f, 0.f, 0.f, 0.f);
#pragma unroll
        for (int k = 0; k < 4; k++) {
            float qv = sm[rgrp + 256 * k];
            acc.x += wv[k].x * qv; acc.y += wv[k].y * qv;
            acc.z += wv[k].z * qv; acc.w += wv[k].w * qv;
        }
        float4* red = (float4*)(sm + H_SZ);              // 1024 float4
        red[rgrp * 4 + col] = acc;
        __syncthreads();
#pragma unroll
        for (int sd = 128; sd >= 1; sd >>= 1) {
            if (rgrp < sd) {
                float4 o = red[(rgrp + sd) * 4 + col];
                float4 m = red[rgrp * 4 + col];
                m.x += o.x; m.y += o.y; m.z += o.z; m.w += o.w;
                red[rgrp * 4 + col] = m;
            }
            __syncthreads();
        }
        if (tid < 4) ((float4*)g_u[hd])[chunk * 4 + tid] = red[tid];

        if (chunk == 0) {   // bq = bias . q, fixed-order
            float v = bias[tid] * sm[tid];
            v = warp_sum(v);
            if (lane == 0) sm[5120 + wid] = v;
            __syncthreads();
            if (tid < 32) {
                float t = sm[5120 + tid];
                t = warp_sum(t);
                if (tid == 0) g_bq[hd] = t;
            }
        }
        __syncthreads();
    }
    gbar();

    // ============ P4: e[hd][s] = ctx[s,:]·u[hd] + bq[hd] =========================
    for (int i = tid; i < 3 * C_SZ; i += TPB) sm[i] = ((const float*)g_u)[i];
    __syncthreads();
    for (int r = gw; r < 3 * S_SZ; r += NBLK * 32) {
        const int hd = r >> 11, srow = r & (S_SZ - 1);
        const float* ctx = (hd == 0) ? ctxL : (hd == 1) ? ctxR : ctxM;
        const float4* c4 = (const float4*)(ctx + (size_t)srow * C_SZ);
        const float4* u4 = (const float4*)(sm + hd * C_SZ);
        float4 wv[8];
#pragma unroll
        for (int k = 0; k < 8; k++) wv[k] = c4[lane + 32 * k];
        float s = 0.f;
#pragma unroll
        for (int k = 0; k < 8; k++) s += dot4(wv[k], u4[lane + 32 * k]);
        s = warp_sum(s);
        if (lane == 0) g_e[hd][srow] = s + g_bq[hd];
    }
    gbar();

    // ============ P5: softmax + weighted column-sum partials =====================
    for (int vb = bid; vb < 192; vb += NBLK) {
        const int cc = vb & 7, rc = (vb >> 3) & 7, hd = vb >> 6;
        // softmax stats over full 2048 logits (deterministic)
        const float e0 = g_e[hd][tid], e1 = g_e[hd][tid + 1024];
        float m = warp_max(fmaxf(e0, e1));
        if (lane == 0) sm[4608 + wid] = m;
        __syncthreads();
        if (tid < 32) {
            float v = sm[4608 + tid];
            v = warp_max(v);
            if (tid == 0) sm[4700] = v;
        }
        __syncthreads();
        const float M = sm[4700];
        float z = expf(e0 - M) + expf(e1 - M);
        z = warp_sum(z);
        __syncthreads();
        if (lane == 0) sm[4608 + wid] = z;
        __syncthreads();
        if (tid < 32) {
            float v = sm[4608 + tid];
            v = warp_sum(v);
            if (tid == 0) sm[4701] = v;
        }
        __syncthreads();
        const float inv = 1.0f / sm[4701];
        if (tid < 256) sm[4096 + tid] = expf(g_e[hd][rc * 256 + tid] - M) * inv;
        __syncthreads();

        // weighted column sum over 256 rows (L2-warm from P4)
        const float* ctx = (hd == 0) ? ctxL : (hd == 1) ? ctxR : ctxM;
        const float4* cp = (const float4*)ctx;
        const int c4col = cc * 32 + lane;
        float4 v[8];
#pragma unroll
        for (int k = 0; k < 8; k++)
            v[k] = cp[(size_t)(rc * 256 + wid + 32 * k) * (C_SZ >> 2) + c4col];
        float4 acc = make_float4(0.f, 0.f, 0.f, 0.f);
#pragma unroll
        for (int k = 0; k < 8; k++) {
            float av = sm[4096 + wid + 32 * k];
            acc.x += v[k].x * av; acc.y += v[k].y * av;
            acc.z += v[k].z * av; acc.w += v[k].w * av;
        }
        float4* red4 = (float4*)sm;
        red4[wid * 32 + lane] = acc;
        __syncthreads();
#pragma unroll
        for (int sd = 16; sd >= 1; sd >>= 1) {
            if (wid < sd) {
                float4 o = red4[(wid + sd) * 32 + lane];
                float4 mm = red4[wid * 32 + lane];
                mm.x += o.x; mm.y += o.y; mm.z += o.z; mm.w += o.w;
                red4[wid * 32 + lane] = mm;
            }
            __syncthreads();
        }
        if (wid == 0) ((float4*)g_wpart[hd][rc])[cc * 32 + lane] = red4[lane];
        __syncthreads();
    }
    gbar();

    // ============ P6: concat_out = tanh(Wc @ [q|l|r|m] + bc) (blocks 0..127) =====
    if (bid < 128) {
        for (int i = tid; i < 4 * H_SZ; i += TPB) {
            float v;
            if (i < H_SZ) v = g_q[i];
            else {
                const int hd = (i >> 10) - 1;
                const int c = i & (H_SZ - 1);
                float s = 0.f;
#pragma unroll
                for (int k = 0; k < NRC; k++) s += g_wpart[hd][k][c];
                v = s;
            }
            sm[i] = v;
        }
        __syncthreads();

        const int row = bid * 8 + (wid >> 2);      // 8 rows/block, 4 warps/row
        const int seg = wid & 3;
        const float4* a  = (const float4*)(Wc + (size_t)row * 4 * H_SZ + seg * H_SZ);
        const float4* x4 = (const float4*)(sm + seg * H_SZ);
        float4 wv[8];
#pragma unroll
        for (int k = 0; k < 8; k++) wv[k] = a[lane + 32 * k];
        float s = 0.f;
#pragma unroll
        for (int k = 0; k < 8; k++) s += dot4(wv[k], x4[lane + 32 * k]);
        s = warp_sum(s);
        if (lane == 0) sm[4096 + (wid >> 2) * 4 + seg] = s;
        __syncthreads();
        if (tid < 8) {
            const float t = sm[4096 + tid * 4] + sm[4096 + tid * 4 + 1] +
                            sm[4096 + tid * 4 + 2] + sm[4096 + tid * 4 + 3];
            const int ro = bid * 8 + tid;
            g_co[ro] = tanhf(t + bc[ro]);
        }
    }
    gbar();

    // ============ P7: output = Wo @ concat_out + bo ===============================
    if (tid < H_SZ) sm[tid] = g_co[tid];
    __syncthreads();
    const float4* x4 = (const float4*)sm;
    for (int r = gw; r < V_SZ; r += NBLK * 32) {
        const float4* a = (const float4*)(Wo + (size_t)r * H_SZ);
        float4 wv[8];
#pragma unroll
        for (int k = 0; k < 8; k++) wv[k] = a[lane + 32 * k];
        float s = 0.f;
#pragma unroll
        for (int k = 0; k < 8; k++) s += dot4(wv[k], x4[lane + 32 * k]);
        s = warp_sum(s);
        if (lane == 0) out[r] = s + bo[r];
    }
}

// ==================================================================================
extern "C" void kernel_launch(void* const* d_in, const int* in_sizes, int n_in,
                              void* d_out, int out_size) {
    const int*   input_ids = (const int*)  d_in[0];
    const float* h0        = (const float*)d_in[1];
    const float* c0        = (const float*)d_in[2];
    const float* ctxL      = (const float*)d_in[3];
    const float* ctxR      = (const float*)d_in[4];
    const float* ctxM      = (const float*)d_in[5];
    const float* emb       = (const float*)d_in[6];
    const float* Wih0      = (const float*)d_in[7];
    const float* Whh0      = (const float*)d_in[8];
    const float* bih0      = (const float*)d_in[9];
    const float* bhh0      = (const float*)d_in[10];
    const float* Wih1      = (const float*)d_in[11];
    const float* Whh1      = (const float*)d_in[12];
    const float* bih1      = (const float*)d_in[13];
    const float* bhh1      = (const float*)d_in[14];
    const float* WL        = (const float*)d_in[15];
    const float* bL        = (const float*)d_in[16];
    const float* WR        = (const float*)d_in[17];
    const float* bR        = (const float*)d_in[18];
    const float* WM        = (const float*)d_in[19];
    const float* bM        = (const float*)d_in[20];
    const float* Wc        = (const float*)d_in[21];
    const float* bc        = (const float*)d_in[22];
    const float* Wo        = (const float*)d_in[23];
    const float* bo        = (const float*)d_in[24];

    float* out   = (float*)d_out;            // [V]
    float* h_new = out + V_SZ;               // [2*H]
    float* c_new = out + V_SZ + 2 * H_SZ;    // [2*H]

    megakernel<<<NBLK, TPB>>>(input_ids, h0, c0, ctxL, ctxR, ctxM, emb,
                              Wih0, Whh0, bih0, bhh0, Wih1, Whh1, bih1, bhh1,
                              WL, bL, WR, bR, WM, bM, Wc, bc, Wo, bo,
                              out, h_new, c_new);
}